// round 7
// baseline (speedup 1.0000x reference)
#include <cuda_runtime.h>
#include <cuda_bf16.h>
#include <math.h>

// Problem constants (fixed shapes from reference setup_inputs)
#define BB 8
#define NN 1024
#define MM 1024
#define DD 64
#define N_ITER 20

// K_SCALE = (1/eps) * log2(e): exp(z/eps) == exp2(z * K_SCALE)
#define K_SCALE 14.426950408889634f
// log2(1/1024 + 1e-8)
#define LOGMU2 (-9.9999852284f)

#define NBLK 148
#define NTHR 1024
#define MAXROWS 57

// persist smem floats: Vs[1024] lognu[1024] a[64] | r bf16[MAXROWS][1024]
#define SMEM_FLOATS (1024 + 1024 + 64)
#define SMEM_PERSIST (SMEM_FLOATS * 4 + MAXROWS * MM * 2)

// gemm dynamic smem: Xsd ull[DD][66] + Ys float[DD][68] + norms
#define GEMM_SMEM (DD * 66 * 8 + DD * 68 * 4 + 2 * 64 * 4)

typedef unsigned long long ull;

// ---- packed f32x2 helpers (sm_103a) ----
__device__ __forceinline__ ull pack2(float lo, float hi) {
    ull r;
    asm("mov.b64 %0, {%1, %2};" : "=l"(r) : "f"(lo), "f"(hi));
    return r;
}
__device__ __forceinline__ void unpack2(float& lo, float& hi, ull v) {
    asm("mov.b64 {%0, %1}, %2;" : "=f"(lo), "=f"(hi) : "l"(v));
}
__device__ __forceinline__ ull add2(ull a, ull b) {
    ull r;
    asm("add.rn.f32x2 %0, %1, %2;" : "=l"(r) : "l"(a), "l"(b));
    return r;
}
__device__ __forceinline__ ull fma2(ull a, ull b, ull c) {
    ull r;
    asm("fma.rn.f32x2 %0, %1, %2, %3;" : "=l"(r) : "l"(a), "l"(b), "l"(c));
    return r;
}
__device__ __forceinline__ float ex2(float x) {
    float r;
    asm("ex2.approx.f32 %0, %1;" : "=f"(r) : "f"(x));
    return r;
}

// Scratch (no allocations allowed -> __device__ globals)
__device__ float g_cs[N_ITER][BB * MM];   // per-iteration column sums
__device__ int g_barc[BB * N_ITER];       // per-(batch,iteration) barrier counters
__device__ float g_lognu2[BB * MM];       // log2(nu + 1e-8)

// ---------------------------------------------------------------------------
// Init: zero cs/barc/cost, compute lognu. 64 blocks x 256 threads.
// ---------------------------------------------------------------------------
__global__ void sk_init(const float* __restrict__ w, float* __restrict__ cost) {
    int idx = blockIdx.x * blockDim.x + threadIdx.x;  // 0..16383
    if (idx < BB) cost[idx] = 0.0f;
    if (idx < BB * N_ITER) g_barc[idx] = 0;
    if (idx < BB * MM) g_lognu2[idx] = __log2f(w[idx] + 1e-8f);
    float4* csf = (float4*)&g_cs[0][0];
    const float4 z = {0.f, 0.f, 0.f, 0.f};
    for (int i = idx; i < N_ITER * BB * MM / 4; i += 16384) csf[i] = z;
}

// ---------------------------------------------------------------------------
// GEMM: C = ||x||^2 + ||y||^2 - 2 x.y. X stored dup-packed ({x,x} f32x2) in
// smem so the inner loop is pure LDS + fma2. Norms computed from smem tiles.
// ---------------------------------------------------------------------------
__global__ void sk_gemm(const float* __restrict__ x, const float* __restrict__ y,
                        float* __restrict__ C) {
    extern __shared__ char gsm[];
    ull* Xsd = (ull*)gsm;                                   // [DD][66]
    float* Ys = (float*)(gsm + DD * 66 * 8);                // [DD][68]
    float* xn_sm = (float*)(gsm + DD * 66 * 8 + DD * 68 * 4);  // [64]
    float* yn_sm = xn_sm + 64;                              // [64]

    int b = blockIdx.z;
    int i0 = blockIdx.y * 64;
    int j0 = blockIdx.x * 64;
    int tid = threadIdx.y * 16 + threadIdx.x;

    const float* xb = x + ((size_t)b * NN + i0) * DD;
    const float* yb = y + ((size_t)b * MM + j0) * DD;
    for (int t = tid; t < 64 * DD; t += 256) {
        int r = t >> 6;
        int d = t & 63;
        float vx = xb[r * DD + d];
        Xsd[d * 66 + r] = pack2(vx, vx);
        Ys[d * 68 + r] = yb[r * DD + d];
    }
    __syncthreads();

    // Row/col norms from smem (threads 0..63: x rows, 64..127: y rows)
    if (tid < 128) {
        int r = tid & 63;
        float s = 0.0f;
        if (tid < 64) {
#pragma unroll 8
            for (int d = 0; d < DD; d++) {
                float lo, hi;
                unpack2(lo, hi, Xsd[d * 66 + r]);
                s += lo * lo;
            }
            xn_sm[r] = s;
        } else {
#pragma unroll 8
            for (int d = 0; d < DD; d++) { float v = Ys[d * 68 + r]; s += v * v; }
            yn_sm[r] = s;
        }
    }

    int ti = threadIdx.y * 4;
    int tj = threadIdx.x * 4;
    ull acc2[4][2];
#pragma unroll
    for (int r = 0; r < 4; r++) { acc2[r][0] = 0ull; acc2[r][1] = 0ull; }

#pragma unroll
    for (int k = 0; k < DD; k++) {
        ulonglong2 a01 = *(const ulonglong2*)&Xsd[k * 66 + ti];      // {x0,x0},{x1,x1}
        ulonglong2 a23 = *(const ulonglong2*)&Xsd[k * 66 + ti + 2];  // {x2,x2},{x3,x3}
        ulonglong2 b2 = *(const ulonglong2*)&Ys[k * 68 + tj];        // y0..y3
        acc2[0][0] = fma2(a01.x, b2.x, acc2[0][0]);
        acc2[0][1] = fma2(a01.x, b2.y, acc2[0][1]);
        acc2[1][0] = fma2(a01.y, b2.x, acc2[1][0]);
        acc2[1][1] = fma2(a01.y, b2.y, acc2[1][1]);
        acc2[2][0] = fma2(a23.x, b2.x, acc2[2][0]);
        acc2[2][1] = fma2(a23.x, b2.y, acc2[2][1]);
        acc2[3][0] = fma2(a23.y, b2.x, acc2[3][0]);
        acc2[3][1] = fma2(a23.y, b2.y, acc2[3][1]);
    }
    __syncthreads();

    float yn0 = yn_sm[tj + 0];
    float yn1 = yn_sm[tj + 1];
    float yn2 = yn_sm[tj + 2];
    float yn3 = yn_sm[tj + 3];
#pragma unroll
    for (int r = 0; r < 4; r++) {
        float a0, a1, a2v, a3;
        unpack2(a0, a1, acc2[r][0]);
        unpack2(a2v, a3, acc2[r][1]);
        float xnv = xn_sm[ti + r];
        size_t off = ((size_t)b * NN + i0 + ti + r) * MM + j0 + tj;
        float4 o;
        o.x = xnv + yn0 - 2.0f * a0;
        o.y = xnv + yn1 - 2.0f * a1;
        o.z = xnv + yn2 - 2.0f * a2v;
        o.w = xnv + yn3 - 2.0f * a3;
        *(float4*)&C[off] = o;
    }
}

// ---------------------------------------------------------------------------
// Phase A, single row (fallback for warps owning 1 row)
// ---------------------------------------------------------------------------
__device__ __forceinline__ void rowA(const float* __restrict__ Crow,
                                     const float* __restrict__ Vs,
                                     uint2* __restrict__ rw,
                                     int lane, float& u, float* a_slot) {
    const ull u2 = pack2(u, u);
    const ull nk2 = pack2(-K_SCALE, -K_SCALE);
    const ulonglong2* cr = (const ulonglong2*)Crow;
    const ulonglong2* vr = (const ulonglong2*)Vs;
    float s0 = 0.f, s1 = 0.f, s2 = 0.f, s3 = 0.f;
#pragma unroll
    for (int k = 0; k < MM / 128; k++) {
        int j4 = lane + 32 * k;
        ulonglong2 c = cr[j4];
        ulonglong2 v = vr[j4];
        ull t01 = fma2(c.x, nk2, add2(v.x, u2));
        ull t23 = fma2(c.y, nk2, add2(v.y, u2));
        float e0, e1, e2, e3;
        unpack2(e0, e1, t01);
        unpack2(e2, e3, t23);
        e0 = ex2(e0); e1 = ex2(e1); e2 = ex2(e2); e3 = ex2(e3);
        __nv_bfloat162 b01 = __floats2bfloat162_rn(e0, e1);
        __nv_bfloat162 b23 = __floats2bfloat162_rn(e2, e3);
        uint2 st;
        st.x = *reinterpret_cast<unsigned*>(&b01);
        st.y = *reinterpret_cast<unsigned*>(&b23);
        rw[j4] = st;
        s0 += e0; s1 += e1; s2 += e2; s3 += e3;
    }
    float s = (s0 + s1) + (s2 + s3);
#pragma unroll
    for (int o = 16; o; o >>= 1) s += __shfl_xor_sync(0xFFFFFFFFu, s, o);
    float unew = 0.f;
    if (lane == 0) {
        float lg = __log2f(s + 1e-6f);
        unew = u + LOGMU2 - lg;
        *a_slot = ex2(LOGMU2 - lg);
    }
    u = __shfl_sync(0xFFFFFFFFu, unew, 0);
}

// ---------------------------------------------------------------------------
// Phase A, TWO rows interleaved in one walk: doubles outstanding loads,
// shares the Vs LDS, single reduction tail.
// ---------------------------------------------------------------------------
__device__ __forceinline__ void rowA2(const float* __restrict__ C0,
                                      const float* __restrict__ C1,
                                      const float* __restrict__ Vs,
                                      uint2* __restrict__ rw0,
                                      uint2* __restrict__ rw1,
                                      int lane, float& u0, float& u1,
                                      float* a0s, float* a1s) {
    const ull nk2 = pack2(-K_SCALE, -K_SCALE);
    const ull u20 = pack2(u0, u0);
    const ull u21 = pack2(u1, u1);
    const ulonglong2* cr0 = (const ulonglong2*)C0;
    const ulonglong2* cr1 = (const ulonglong2*)C1;
    const ulonglong2* vr = (const ulonglong2*)Vs;
    float s0 = 0.f, s1 = 0.f, s2 = 0.f, s3 = 0.f;
    float t0 = 0.f, t1 = 0.f, t2 = 0.f, t3 = 0.f;
#pragma unroll
    for (int k = 0; k < MM / 128; k++) {
        int j4 = lane + 32 * k;
        ulonglong2 c0 = cr0[j4];
        ulonglong2 c1 = cr1[j4];
        ulonglong2 v = vr[j4];
        ull p01 = fma2(c0.x, nk2, add2(v.x, u20));
        ull p23 = fma2(c0.y, nk2, add2(v.y, u20));
        ull q01 = fma2(c1.x, nk2, add2(v.x, u21));
        ull q23 = fma2(c1.y, nk2, add2(v.y, u21));
        float e0, e1, e2, e3, f0, f1, f2, f3;
        unpack2(e0, e1, p01); unpack2(e2, e3, p23);
        unpack2(f0, f1, q01); unpack2(f2, f3, q23);
        e0 = ex2(e0); e1 = ex2(e1); e2 = ex2(e2); e3 = ex2(e3);
        f0 = ex2(f0); f1 = ex2(f1); f2 = ex2(f2); f3 = ex2(f3);
        __nv_bfloat162 b01 = __floats2bfloat162_rn(e0, e1);
        __nv_bfloat162 b23 = __floats2bfloat162_rn(e2, e3);
        __nv_bfloat162 d01 = __floats2bfloat162_rn(f0, f1);
        __nv_bfloat162 d23 = __floats2bfloat162_rn(f2, f3);
        uint2 sa, sb;
        sa.x = *reinterpret_cast<unsigned*>(&b01);
        sa.y = *reinterpret_cast<unsigned*>(&b23);
        sb.x = *reinterpret_cast<unsigned*>(&d01);
        sb.y = *reinterpret_cast<unsigned*>(&d23);
        rw0[j4] = sa;
        rw1[j4] = sb;
        s0 += e0; s1 += e1; s2 += e2; s3 += e3;
        t0 += f0; t1 += f1; t2 += f2; t3 += f3;
    }
    float s = (s0 + s1) + (s2 + s3);
    float t = (t0 + t1) + (t2 + t3);
#pragma unroll
    for (int o = 16; o; o >>= 1) {
        s += __shfl_xor_sync(0xFFFFFFFFu, s, o);
        t += __shfl_xor_sync(0xFFFFFFFFu, t, o);
    }
    float nu0 = 0.f, nu1 = 0.f;
    if (lane == 0) {
        float lg = __log2f(s + 1e-6f);
        nu0 = u0 + LOGMU2 - lg;
        *a0s = ex2(LOGMU2 - lg);
        float lh = __log2f(t + 1e-6f);
        nu1 = u1 + LOGMU2 - lh;
        *a1s = ex2(LOGMU2 - lh);
    }
    u0 = __shfl_sync(0xFFFFFFFFu, nu0, 0);
    u1 = __shfl_sync(0xFFFFFFFFu, nu1, 0);
}

// ---------------------------------------------------------------------------
// Final row: pi = exp2(C*(-K) + v + u), cost partial = sum pi*C
// ---------------------------------------------------------------------------
__device__ __forceinline__ void rowFinal(const float* __restrict__ Crow,
                                         const float* __restrict__ Vs,
                                         float* __restrict__ pirow,
                                         int lane, float u, float* cost_b) {
    const ull u2 = pack2(u, u);
    const ull nk2 = pack2(-K_SCALE, -K_SCALE);
    const float4* cf = (const float4*)Crow;
    const ulonglong2* vr = (const ulonglong2*)Vs;
    float4* pr = (float4*)pirow;
    float s = 0.f;
#pragma unroll
    for (int k = 0; k < MM / 128; k++) {
        int j4 = lane + 32 * k;
        float4 c = cf[j4];
        ulonglong2 v = vr[j4];
        ull c01 = pack2(c.x, c.y);
        ull c23 = pack2(c.z, c.w);
        ull t01 = fma2(c01, nk2, add2(v.x, u2));
        ull t23 = fma2(c23, nk2, add2(v.y, u2));
        float e0, e1, e2, e3;
        unpack2(e0, e1, t01);
        unpack2(e2, e3, t23);
        float4 p;
        p.x = ex2(e0); p.y = ex2(e1); p.z = ex2(e2); p.w = ex2(e3);
        pr[j4] = p;
        s = fmaf(p.x, c.x, s);
        s = fmaf(p.y, c.y, s);
        s = fmaf(p.z, c.z, s);
        s = fmaf(p.w, c.w, s);
    }
#pragma unroll
    for (int o = 16; o; o >>= 1) s += __shfl_xor_sync(0xFFFFFFFFu, s, o);
    if (lane == 0) atomicAdd(cost_b, s);
}

// ---------------------------------------------------------------------------
// Persistent kernel: 148 blocks, 1/SM. Each block belongs to exactly ONE
// batch (18-19 blocks per batch, 53-57 rows per block); per-batch barriers.
// ---------------------------------------------------------------------------
__global__ void __launch_bounds__(NTHR, 1)
sk_persist(const float* __restrict__ C, float* __restrict__ pi,
           float* __restrict__ cost) {
    extern __shared__ float sm[];
    float* Vs = sm;                    // [1024]
    float* lognu_sm = sm + 1024;       // [1024]
    float* a_sm = sm + 2048;           // [64]
    uint2* r_sm = (uint2*)(sm + SMEM_FLOATS);  // [MAXROWS][256] = bf16[57][1024]

    const int blk = blockIdx.x;
    const int tid = threadIdx.x;
    const int b = (blk * BB) / NBLK;
    const int lb0 = (b * NBLK + BB - 1) / BB;
    const int lb1 = ((b + 1) * NBLK + BB - 1) / BB;
    const int nb = lb1 - lb0;                  // blocks in this batch (18/19)
    const int lb = blk - lb0;
    const int rs = (lb * NN) / nb;
    const int nr = ((lb + 1) * NN) / nb - rs;  // 53..57
    const int r0 = b * NN + rs;                // global start row

    for (int j = tid; j < MM; j += NTHR) {
        lognu_sm[j] = g_lognu2[b * MM + j];
        Vs[j] = 0.0f;
    }
    __syncthreads();

    const int warp = tid >> 5, lane = tid & 31;
    const bool has1 = (32 + warp) < nr;
    float u0 = 0.0f, u1 = 0.0f;

    // Phase-B mapping: 2 row-groups x 512 col-pair threads
    const int grp = tid >> 9;
    const int j2 = tid & 511;
    const int nrh = nr >> 1;
    const int p0 = grp ? nrh : 0;
    const int p1 = grp ? nr : nrh;

    for (int it = 0; it < N_ITER; it++) {
        // ---- Phase 0: V update from previous colsum ----
        if (it > 0) {
            const float* cs = g_cs[it - 1] + b * MM;
            for (int j = tid; j < MM; j += NTHR)
                Vs[j] += lognu_sm[j] - __log2f(cs[j] + 1e-6f);
            __syncthreads();
        }

        // ---- Phase A: warp-per-row, 2 rows interleaved ----
        if (has1)
            rowA2(C + (size_t)(r0 + warp) * MM, C + (size_t)(r0 + 32 + warp) * MM,
                  Vs, r_sm + (size_t)warp * 256, r_sm + (size_t)(warp + 32) * 256,
                  lane, u0, u1, a_sm + warp, a_sm + warp + 32);
        else
            rowA(C + (size_t)(r0 + warp) * MM, Vs, r_sm + (size_t)warp * 256,
                 lane, u0, a_sm + warp);
        __syncthreads();

        // ---- Phase B: column partials from bf16 r, scaled by a ----
        {
            float ax = 0.f, ay = 0.f;
            const __nv_bfloat162* rb = (const __nv_bfloat162*)r_sm;
            for (int rl = p0; rl < p1; rl++) {
                float2 rv = __bfloat1622float2(rb[(size_t)rl * 512 + j2]);
                float a = a_sm[rl];
                ax = fmaf(rv.x, a, ax);
                ay = fmaf(rv.y, a, ay);
            }
            float* cso = g_cs[it] + b * MM;
            atomicAdd(&cso[2 * j2 + 0], ax);
            atomicAdd(&cso[2 * j2 + 1], ay);
        }

        // ---- per-batch barrier ----
        __threadfence();
        __syncthreads();
        if (tid == 0) {
            int slot = b * N_ITER + it;
            atomicAdd(&g_barc[slot], 1);
            while (*((volatile int*)&g_barc[slot]) < nb) __nanosleep(32);
        }
        __syncthreads();
    }

    // ---- Final V update ----
    {
        const float* cs = g_cs[N_ITER - 1] + b * MM;
        for (int j = tid; j < MM; j += NTHR)
            Vs[j] += lognu_sm[j] - __log2f(cs[j] + 1e-6f);
    }
    __syncthreads();

    // ---- Final pi + cost ----
    rowFinal(C + (size_t)(r0 + warp) * MM, Vs, pi + (size_t)(r0 + warp) * MM,
             lane, u0, &cost[b]);
    if (has1)
        rowFinal(C + (size_t)(r0 + 32 + warp) * MM, Vs,
                 pi + (size_t)(r0 + 32 + warp) * MM, lane, u1, &cost[b]);
}

// ---------------------------------------------------------------------------
// Launch. Output: [0,8) cost | [8, 8+B*N*M) pi | then C
// ---------------------------------------------------------------------------
extern "C" void kernel_launch(void* const* d_in, const int* in_sizes, int n_in,
                              void* d_out, int out_size) {
    const float* x = (const float*)d_in[0];
    const float* y = (const float*)d_in[1];
    const float* w = (const float*)d_in[2];
    float* cost = (float*)d_out;
    float* pi = cost + BB;
    float* C = pi + (size_t)BB * NN * MM;

    cudaFuncSetAttribute(sk_persist, cudaFuncAttributeMaxDynamicSharedMemorySize,
                         SMEM_PERSIST);
    cudaFuncSetAttribute(sk_gemm, cudaFuncAttributeMaxDynamicSharedMemorySize,
                         GEMM_SMEM);

    sk_init<<<64, 256>>>(w, cost);
    sk_gemm<<<dim3(MM / 64, NN / 64, BB), dim3(16, 16), GEMM_SMEM>>>(x, y, C);
    sk_persist<<<NBLK, NTHR, SMEM_PERSIST>>>(C, pi, cost);
}